// round 9
// baseline (speedup 1.0000x reference)
#include <cuda_runtime.h>
#include <math.h>

#define TT 4096
#define DD 1024
#define NSCAN 128     // scan CTAs (grid barrier participants)
#define NWORK 168     // persistent GEMM worker CTAs
#define NCTA_TOT (NSCAN + NWORK)   // 296 = exactly 2 CTAs/SM x 148 SMs (wave-1 resident)
#define STH 256

// g_sync layout (padded to separate L2 lines):
//   [0]        barrier counter (red.add target, hot-polled by scan tid0s)
//   [32]       scan progress (steps done), published by scan CTA0, polled by workers
//   [64..95]   g_done[b]: # of input-projection tiles finished for row-block b (target 24)
#define CNT_OFF  0
#define PRG_OFF  32
#define DONE_OFF 64

// ---------------- scratch (device globals: no allocation allowed) ----------------
__device__ float g_Ar[TT * DD];   // xs@Wir + bir
__device__ float g_Az[TT * DD];   // xs@Wiz + biz
__device__ float g_An[TT * DD];   // xs@Win + bin
__device__ float g_ys[TT * DD];   // scan outputs
__device__ float g_lin[TT * DD];  // xs + relu(ys)@Wl + bl (pre-LN)
__device__ float g_h[2][DD];      // ping-pong hidden state
__device__ unsigned g_sync[96];   // see layout above

// ---------------- helpers ----------------
__device__ __forceinline__ float4 ldcg4(const float4* p) {
    float4 v;
    asm volatile("ld.global.cg.v4.f32 {%0,%1,%2,%3}, [%4];"
                 : "=f"(v.x), "=f"(v.y), "=f"(v.z), "=f"(v.w) : "l"(p));
    return v;
}
__device__ __forceinline__ unsigned ld_acquire_u32(const unsigned* p) {
    unsigned v;
    asm volatile("ld.acquire.gpu.global.u32 %0, [%1];" : "=r"(v) : "l"(p));
    return v;
}
__device__ __forceinline__ void red_release_add(unsigned* p) {
    asm volatile("red.release.gpu.global.add.u32 [%0], 1;" :: "l"(p) : "memory");
}
__device__ __forceinline__ void st_release_u32(unsigned* p, unsigned v) {
    asm volatile("st.release.gpu.global.u32 [%0], %1;" :: "l"(p), "r"(v) : "memory");
}
__device__ __forceinline__ float fast_sigmoid(float x) {
    return 1.f / (1.f + __expf(-x));
}
__device__ __forceinline__ float fast_tanh(float x) {
    return 1.f - 2.f / (1.f + __expf(2.f * x));
}

// ---------------- GEMM tile: C[128,128] = op(A)[by]@B[bx] + bias (+resid) ----------------
// BK=8, 256 threads, 8x8 micro-tile, scalar FFMA (f32x2 regressed in R6 -> reverted).
template <bool RELU, bool RESID>
__device__ void gemm_tile(const float* __restrict__ A, const float* __restrict__ B,
                          const float* __restrict__ bias, const float* __restrict__ resid,
                          float* __restrict__ C, int bx, int by,
                          float* As /*8*128*/, float* Bs /*8*128*/)
{
    const int tid = threadIdx.x;
    const int arow = tid >> 1;         // 0..127
    const int acol = (tid & 1) << 2;   // 0 or 4
    const int brow = tid >> 5;         // 0..7
    const int bcol = (tid & 31) << 2;  // 0..124
    const int tx = tid & 15;
    const int ty = tid >> 4;

    const float* Ab = A + (size_t)by * 128 * DD;
    const float* Bb = B + bx * 128;

    float acc[8][8];
    #pragma unroll
    for (int i = 0; i < 8; ++i)
        #pragma unroll
        for (int jj = 0; jj < 8; ++jj) acc[i][jj] = 0.f;

    float4 aReg = *(const float4*)(Ab + (size_t)arow * DD + acol);
    float4 bReg = *(const float4*)(Bb + (size_t)brow * DD + bcol);

    for (int k0 = 0; k0 < DD; k0 += 8) {
        float4 av = aReg;
        if (RELU) {
            av.x = fmaxf(av.x, 0.f); av.y = fmaxf(av.y, 0.f);
            av.z = fmaxf(av.z, 0.f); av.w = fmaxf(av.w, 0.f);
        }
        As[(acol + 0) * 128 + arow] = av.x;
        As[(acol + 1) * 128 + arow] = av.y;
        As[(acol + 2) * 128 + arow] = av.z;
        As[(acol + 3) * 128 + arow] = av.w;
        *(float4*)&Bs[brow * 128 + bcol] = bReg;
        __syncthreads();
        if (k0 + 8 < DD) {   // prefetch next tile during compute
            aReg = *(const float4*)(Ab + (size_t)arow * DD + (k0 + 8) + acol);
            bReg = *(const float4*)(Bb + (size_t)(k0 + 8 + brow) * DD + bcol);
        }
        #pragma unroll
        for (int kk = 0; kk < 8; ++kk) {
            float a[8], b[8];
            *(float4*)&a[0] = *(const float4*)&As[kk * 128 + ty * 8];
            *(float4*)&a[4] = *(const float4*)&As[kk * 128 + ty * 8 + 4];
            *(float4*)&b[0] = *(const float4*)&Bs[kk * 128 + tx * 8];
            *(float4*)&b[4] = *(const float4*)&Bs[kk * 128 + tx * 8 + 4];
            #pragma unroll
            for (int i = 0; i < 8; ++i)
                #pragma unroll
                for (int jj = 0; jj < 8; ++jj)
                    acc[i][jj] = fmaf(a[i], b[jj], acc[i][jj]);
        }
        __syncthreads();
    }

    const int nbase = bx * 128 + tx * 8;
    const float4 b0 = *(const float4*)(bias + nbase);
    const float4 b1 = *(const float4*)(bias + nbase + 4);
    #pragma unroll
    for (int i = 0; i < 8; ++i) {
        const int m = by * 128 + ty * 8 + i;
        float4 c0, c1;
        c0.x = acc[i][0] + b0.x; c0.y = acc[i][1] + b0.y;
        c0.z = acc[i][2] + b0.z; c0.w = acc[i][3] + b0.w;
        c1.x = acc[i][4] + b1.x; c1.y = acc[i][5] + b1.y;
        c1.z = acc[i][6] + b1.z; c1.w = acc[i][7] + b1.w;
        if (RESID) {
            const float4 r0 = *(const float4*)(resid + (size_t)m * DD + nbase);
            const float4 r1 = *(const float4*)(resid + (size_t)m * DD + nbase + 4);
            c0.x += r0.x; c0.y += r0.y; c0.z += r0.z; c0.w += r0.w;
            c1.x += r1.x; c1.y += r1.y; c1.z += r1.z; c1.w += r1.w;
        }
        *(float4*)(C + (size_t)m * DD + nbase)     = c0;
        *(float4*)(C + (size_t)m * DD + nbase + 4) = c1;
    }
}

// ---------------- scan role (CTAs 0..127) ----------------
// Each CTA owns 8 columns j=cta*8+w, one warp per column. Recurrent weights
// register-resident (24 float4/lane). A-prefetch gated on worker progress.
__device__ void scan_role(const float* __restrict__ Whr, const float* __restrict__ Whz,
                          const float* __restrict__ Whn, const float* __restrict__ bhn,
                          float* hs)
{
    float4* hs4v = (float4*)hs;
    const int tid  = threadIdx.x;
    const int cta  = blockIdx.x;
    const int w    = tid >> 5;
    const int lane = tid & 31;
    const int j    = cta * 8 + w;

    // one-time weight load into registers (issued before the g_done wait so the
    // long-latency loads complete while we wait for the first A row-block)
    float4 wr[8], wz[8], wn[8];
    #pragma unroll
    for (int i = 0; i < 8; ++i) {
        const int k = 4 * (lane + 32 * i);
        wr[i] = make_float4(Whr[(size_t)(k + 0) * DD + j], Whr[(size_t)(k + 1) * DD + j],
                            Whr[(size_t)(k + 2) * DD + j], Whr[(size_t)(k + 3) * DD + j]);
        wz[i] = make_float4(Whz[(size_t)(k + 0) * DD + j], Whz[(size_t)(k + 1) * DD + j],
                            Whz[(size_t)(k + 2) * DD + j], Whz[(size_t)(k + 3) * DD + j]);
        wn[i] = make_float4(Whn[(size_t)(k + 0) * DD + j], Whn[(size_t)(k + 1) * DD + j],
                            Whn[(size_t)(k + 2) * DD + j], Whn[(size_t)(k + 3) * DD + j]);
    }
    const float bh = bhn[j];

    // wait for input-projection row-block 0, then prefetch t=0 terms
    if (tid == 0) {
        while (ld_acquire_u32(&g_sync[DONE_OFF + 0]) < 24) __nanosleep(256);
    }
    __syncthreads();
    float ar = 0.f, az = 0.f, an = 0.f;
    if (lane == 0) { ar = g_Ar[j]; az = g_Az[j]; an = g_An[j]; }

    for (int t = 0; t < TT; ++t) {
        // h broadcast -> SMEM; .cg to bypass L1 (stale ping-pong copy from t-2)
        hs4v[tid] = ldcg4(((const float4*)g_h[t & 1]) + tid);
        __syncthreads();

        float accr = 0.f, accz = 0.f, accn = 0.f;
        #pragma unroll
        for (int i = 0; i < 8; ++i) {
            const float4 hv = hs4v[lane + 32 * i];
            accr = fmaf(hv.x, wr[i].x, fmaf(hv.y, wr[i].y, fmaf(hv.z, wr[i].z, fmaf(hv.w, wr[i].w, accr))));
            accz = fmaf(hv.x, wz[i].x, fmaf(hv.y, wz[i].y, fmaf(hv.z, wz[i].z, fmaf(hv.w, wz[i].w, accz))));
            accn = fmaf(hv.x, wn[i].x, fmaf(hv.y, wn[i].y, fmaf(hv.z, wn[i].z, fmaf(hv.w, wn[i].w, accn))));
        }
        #pragma unroll
        for (int off = 16; off > 0; off >>= 1) {
            accr += __shfl_xor_sync(0xffffffffu, accr, off);
            accz += __shfl_xor_sync(0xffffffffu, accz, off);
            accn += __shfl_xor_sync(0xffffffffu, accn, off);
        }
        if (lane == 0) {
            const float hprev = hs[j];
            const float r  = fast_sigmoid(ar + accr);
            const float z  = fast_sigmoid(az + accz);
            const float n  = fast_tanh(an + r * (accn + bh));
            const float hn = (1.f - z) * n + z * hprev;
            g_h[(t + 1) & 1][j] = hn;
            g_ys[(size_t)t * DD + j] = hn;
        }

        const int tn = t + 1;
        // row-block boundary: gate on input-projection workers (CTA-uniform)
        if (tn < TT && (tn & 127) == 0) {
            if (tid == 0) {
                while (ld_acquire_u32(&g_sync[DONE_OFF + (tn >> 7)]) < 24) __nanosleep(256);
            }
            __syncthreads();
        }
        if (lane == 0 && tn < TT) {     // prefetch next step's A terms
            const size_t o = (size_t)tn * DD + j;
            ar = g_Ar[o]; az = g_Az[o]; an = g_An[o];
        }
        __syncthreads();                // all h/ys writes + hs reads done

        // grid barrier across the 128 scan CTAs
        if (tid == 0) {
            red_release_add(&g_sync[CNT_OFF]);
            const unsigned target = (unsigned)tn * NSCAN;
            while (ld_acquire_u32(&g_sync[CNT_OFF]) < target) { }
            if (cta == 0) st_release_u32(&g_sync[PRG_OFF], (unsigned)tn);  // publish progress
        }
        __syncthreads();
    }
}

// ---------------- worker role (CTAs 128..295) ----------------
__device__ void worker_role(int wid,
    const float* __restrict__ xs,
    const float* __restrict__ Wir, const float* __restrict__ Wiz, const float* __restrict__ Win,
    const float* __restrict__ bir, const float* __restrict__ biz, const float* __restrict__ bin_,
    const float* __restrict__ Wl,  const float* __restrict__ bl,
    float* smem)
{
    float* As = smem;
    float* Bs = smem + 8 * 128;
    const int tid = threadIdx.x;

    // phase 1: input projections, 768 tiles ordered by row-block so early blocks finish first
    for (int tile = wid; tile < 32 * 24; tile += NWORK) {
        const int by  = tile / 24;
        const int rem = tile - by * 24;
        const int z   = rem >> 3;
        const int bx  = rem & 7;
        const float* B    = (z == 0) ? Wir : (z == 1) ? Wiz : Win;
        const float* bias = (z == 0) ? bir : (z == 1) ? biz : bin_;
        float*       C    = (z == 0) ? g_Ar : (z == 1) ? g_Az : g_An;
        gemm_tile<false, false>(xs, B, bias, nullptr, C, bx, by, As, Bs);
        __syncthreads();                          // all threads' C stores done
        if (tid == 0) red_release_add(&g_sync[DONE_OFF + by]);
    }

    // phase 2: output dense, chasing scan progress (gated per row-block)
    for (int tile = wid; tile < 32 * 8; tile += NWORK) {
        const int by = tile >> 3;
        const int bx = tile & 7;
        if (tid == 0) {
            const unsigned need = (unsigned)(by + 1) * 128;
            while (ld_acquire_u32(&g_sync[PRG_OFF]) < need) __nanosleep(512);
        }
        __syncthreads();
        gemm_tile<true, true>(g_ys, Wl, bl, xs, g_lin, bx, by, As, Bs);
    }
}

// ---------------- mega kernel: scan + workers, all wave-1 resident ----------------
__global__ void __launch_bounds__(STH, 2) mega_kernel(
    const float* __restrict__ xs,
    const float* __restrict__ Whr, const float* __restrict__ Whz,
    const float* __restrict__ Whn, const float* __restrict__ bhn,
    const float* __restrict__ Wir, const float* __restrict__ Wiz, const float* __restrict__ Win,
    const float* __restrict__ bir, const float* __restrict__ biz, const float* __restrict__ bin_,
    const float* __restrict__ Wl,  const float* __restrict__ bl)
{
    __shared__ float smem[2048];   // scan: hs[1024]; workers: As+Bs (8KB)
    if (blockIdx.x < NSCAN)
        scan_role(Whr, Whz, Whn, bhn, smem);
    else
        worker_role(blockIdx.x - NSCAN, xs, Wir, Wiz, Win, bir, biz, bin_, Wl, bl, smem);
}

// ---------------- layernorm over last dim ----------------
__global__ void __launch_bounds__(256) ln_kernel(
    const float* __restrict__ lin, const float* __restrict__ scale,
    const float* __restrict__ bias, float* __restrict__ out)
{
    const int t = blockIdx.x;
    const int tid = threadIdx.x;
    const int w = tid >> 5, lane = tid & 31;
    const float4 v = ((const float4*)(lin + (size_t)t * DD))[tid];
    float s = v.x + v.y + v.z + v.w;
    float q = v.x * v.x + v.y * v.y + v.z * v.z + v.w * v.w;
    #pragma unroll
    for (int off = 16; off > 0; off >>= 1) {
        s += __shfl_xor_sync(0xffffffffu, s, off);
        q += __shfl_xor_sync(0xffffffffu, q, off);
    }
    __shared__ float ss[8], qs[8];
    __shared__ float sMean, sInv;
    if (lane == 0) { ss[w] = s; qs[w] = q; }
    __syncthreads();
    if (tid == 0) {
        float S = 0.f, Q = 0.f;
        #pragma unroll
        for (int i = 0; i < 8; ++i) { S += ss[i]; Q += qs[i]; }
        const float mean = S * (1.0f / DD);
        const float var  = Q * (1.0f / DD) - mean * mean;
        sMean = mean;
        sInv  = rsqrtf(var + 1e-6f);
    }
    __syncthreads();
    const float mean = sMean, inv = sInv;
    const float4 sc = ((const float4*)scale)[tid];
    const float4 bi = ((const float4*)bias)[tid];
    float4 o;
    o.x = (v.x - mean) * inv * sc.x + bi.x;
    o.y = (v.y - mean) * inv * sc.y + bi.y;
    o.z = (v.z - mean) * inv * sc.z + bi.z;
    o.w = (v.w - mean) * inv * sc.w + bi.w;
    ((float4*)(out + (size_t)t * DD))[tid] = o;
}

// ---------------- launch ----------------
extern "C" void kernel_launch(void* const* d_in, const int* in_sizes, int n_in,
                              void* d_out, int out_size) {
    (void)in_sizes; (void)n_in; (void)out_size;
    const float* xs   = (const float*)d_in[0];
    const float* hini = (const float*)d_in[1];
    const float* Wir  = (const float*)d_in[2];
    const float* Wiz  = (const float*)d_in[3];
    const float* Win  = (const float*)d_in[4];
    const float* bir  = (const float*)d_in[5];
    const float* biz  = (const float*)d_in[6];
    const float* bin_ = (const float*)d_in[7];
    const float* Whr  = (const float*)d_in[8];
    const float* Whz  = (const float*)d_in[9];
    const float* Whn  = (const float*)d_in[10];
    const float* bhn  = (const float*)d_in[11];
    const float* Wl   = (const float*)d_in[12];
    const float* bl   = (const float*)d_in[13];
    const float* lns  = (const float*)d_in[14];
    const float* lnb  = (const float*)d_in[15];
    float* out = (float*)d_out;

    float *lin, *hb;
    unsigned* syn;
    cudaGetSymbolAddress((void**)&lin, g_lin);
    cudaGetSymbolAddress((void**)&hb,  g_h);
    cudaGetSymbolAddress((void**)&syn, g_sync);

    // per-replay state reset (device globals persist across graph replays!)
    cudaMemsetAsync(syn, 0, 96 * sizeof(unsigned), 0);
    cudaMemcpyAsync(hb, hini, DD * sizeof(float), cudaMemcpyDeviceToDevice, 0);

    // one resident mega-kernel: 128 scan CTAs + 168 GEMM workers, fully overlapped
    mega_kernel<<<NCTA_TOT, STH>>>(xs, Whr, Whz, Whn, bhn,
                                   Wir, Wiz, Win, bir, biz, bin_, Wl, bl);

    ln_kernel<<<TT, 256>>>(lin, lns, lnb, out);
}